// round 13
// baseline (speedup 1.0000x reference)
#include <cuda_runtime.h>
#include <cstdint>

#define NN      8192
#define THREADS 640                   // 20 warps per CTA
#define NCTA    148
#define WPC     (THREADS / 32)        // 20
#define NSEG    32                    // column segments of 256 cols
#define SEGC    256
#define NRG     92                    // rowgroups (32*92 = 2944 working warps)
#define RU      5                     // rows per inner iteration (15 values + pad)
#define LBLKS   128                   // loss kernel grid (128*256 = 4 threads/node)

// scratch: __device__ globals (allocation-free rule).
// g_dotpart: layout [row][seg][3]; every slot overwritten by exactly one
//   warp per launch -> deterministic, no zeroing needed.
// g_deg: accumulated via float atomics of integer-valued addends (bit-exact,
//   order-independent); zero at load, re-zeroed by the loss kernel each launch.
__device__ float g_dotpart[NN * NSEG * 3];      // 3.1 MB
__device__ float g_deg[NN];
__device__ float g_losspart[LBLKS];
__device__ int   g_done;                        // reset by the unique last block

__device__ __forceinline__ float warp_sum(float v) {
    v += __shfl_down_sync(0xFFFFFFFFu, v, 16);
    v += __shfl_down_sync(0xFFFFFFFFu, v, 8);
    v += __shfl_down_sync(0xFFFFFFFFu, v, 4);
    v += __shfl_down_sync(0xFFFFFFFFu, v, 2);
    v += __shfl_down_sync(0xFFFFFFFFu, v, 1);
    return v;
}

// one butterfly step: live values v[0..L-1] -> v[0..L/2-1], width W
// NOTE: all 32 lanes must be convergent.
template <int L, int W>
__device__ __forceinline__ void bstep(float* v, int lane) {
    const int hi = lane & W;
    #pragma unroll
    for (int j = 0; j < L / 2; j++) {
        const float sent = hi ? v[j] : v[j + L / 2];
        const float got  = __shfl_xor_sync(0xFFFFFFFFu, sent, W);
        v[j] = (hi ? v[j + L / 2] : v[j]) + got;
    }
}

// ---------- kernel A: one streaming pass over A ----------
__global__ void __launch_bounds__(THREADS, 1)
spmm_kernel(const float* __restrict__ pred1,
            const float* __restrict__ pred2,
            const float* __restrict__ A) {
    const int tid  = threadIdx.x;
    const int lane = tid & 31;
    const int warp = tid >> 5;

    const int w    = blockIdx.x * WPC + warp;
    const int seg  = w & (NSEG - 1);
    const int rg   = w >> 5;
    const int col0 = seg * SEGC + lane * 8;        // this lane's 8 columns
    const bool active = (rg < NRG);
    const int r0   = active ? (rg * NN) / NRG : 0;
    const int r1   = active ? ((rg + 1) * NN) / NRG : 0;

    // butterfly-output indexing for this lane (value k -> row k/3, dim k%3)
    const int bk   = lane >> 1;
    const int bkr  = bk / 3;
    const int bkd  = bk - bkr * 3;
    const bool bwr = ((lane & 1) == 0) && (bk < 15);

    // hoist p = pred2 - pred1 for this lane's 8 columns: p[jc][d], 24 regs
    float p[8][3];
    {
        const float4* q1 = reinterpret_cast<const float4*>(pred1 + (size_t)col0 * 3);
        const float4* q2 = reinterpret_cast<const float4*>(pred2 + (size_t)col0 * 3);
        float tmp[24];
        #pragma unroll
        for (int k = 0; k < 6; k++) {
            const float4 a = q2[k];
            const float4 b = q1[k];
            tmp[4 * k + 0] = a.x - b.x;
            tmp[4 * k + 1] = a.y - b.y;
            tmp[4 * k + 2] = a.z - b.z;
            tmp[4 * k + 3] = a.w - b.w;
        }
        #pragma unroll
        for (int j = 0; j < 24; j++) p[j / 3][j % 3] = tmp[j];
    }

    float dg[8];
    #pragma unroll
    for (int j = 0; j < 8; j++) dg[j] = 0.0f;

    const float4* __restrict__ Abase =
        reinterpret_cast<const float4*>(A + (size_t)r0 * NN + col0);
    const int stride4 = NN / 4;
    const int rows = r1 - r0;

    int r = 0;
    for (; r + RU <= rows; r += RU) {
        // front-batch 2*RU = 10 independent loads
        float4 av[RU][2];
        #pragma unroll
        for (int k = 0; k < RU; k++) {
            const float4* rp = Abase + (size_t)(r + k) * stride4;
            av[k][0] = __ldcs(rp);
            av[k][1] = __ldcs(rp + 1);
        }

        float v[16];
        #pragma unroll
        for (int k = 0; k < RU; k++) {
            const float4 a0 = av[k][0], a1 = av[k][1];
            #pragma unroll
            for (int d = 0; d < 3; d++) {
                v[k * 3 + d] =
                    a0.x * p[0][d] + a0.y * p[1][d] + a0.z * p[2][d] + a0.w * p[3][d] +
                    a1.x * p[4][d] + a1.y * p[5][d] + a1.z * p[6][d] + a1.w * p[7][d];
            }
            dg[0] += a0.x; dg[1] += a0.y; dg[2] += a0.z; dg[3] += a0.w;
            dg[4] += a1.x; dg[5] += a1.y; dg[6] += a1.z; dg[7] += a1.w;
        }
        v[15] = 0.0f;                              // pad to 16

        // multi-value butterfly: after 5 steps, lane pair floor(l/2)
        // holds the full 32-lane sum of value floor(l/2)
        bstep<16, 16>(v, lane);
        bstep<8, 8>(v, lane);
        bstep<4, 4>(v, lane);
        bstep<2, 2>(v, lane);
        v[0] += __shfl_xor_sync(0xFFFFFFFFu, v[0], 1);

        // transposed store: [row][seg][3]
        if (bwr)
            g_dotpart[((size_t)(r0 + r + bkr) * NSEG + seg) * 3 + bkd] = v[0];
    }

    // tail rows (<= RU-1): plain warp reductions, fully convergent
    for (; r < rows; r++) {
        const float4* rp = Abase + (size_t)r * stride4;
        const float4 a0 = __ldcs(rp);
        const float4 a1 = __ldcs(rp + 1);
        float t0 = warp_sum(
            a0.x * p[0][0] + a0.y * p[1][0] + a0.z * p[2][0] + a0.w * p[3][0] +
            a1.x * p[4][0] + a1.y * p[5][0] + a1.z * p[6][0] + a1.w * p[7][0]);
        float t1 = warp_sum(
            a0.x * p[0][1] + a0.y * p[1][1] + a0.z * p[2][1] + a0.w * p[3][1] +
            a1.x * p[4][1] + a1.y * p[5][1] + a1.z * p[6][1] + a1.w * p[7][1]);
        float t2 = warp_sum(
            a0.x * p[0][2] + a0.y * p[1][2] + a0.z * p[2][2] + a0.w * p[3][2] +
            a1.x * p[4][2] + a1.y * p[5][2] + a1.z * p[6][2] + a1.w * p[7][2]);
        dg[0] += a0.x; dg[1] += a0.y; dg[2] += a0.z; dg[3] += a0.w;
        dg[4] += a1.x; dg[5] += a1.y; dg[6] += a1.z; dg[7] += a1.w;
        if (lane == 0) {
            float* dst = g_dotpart + ((size_t)(r0 + r) * NSEG + seg) * 3;
            dst[0] = t0; dst[1] = t1; dst[2] = t2;
        }
    }

    // flush deg: exact (integer-valued) float atomics, spread addresses,
    // outside the hot loop
    if (active) {
        #pragma unroll
        for (int j = 0; j < 8; j++)
            atomicAdd(&g_deg[col0 + j], dg[j]);
    }
}

// ---------- kernel B: coalesced loss + fused final + deg re-zero ----------
__global__ void __launch_bounds__(256)
loss_kernel(const float* __restrict__ pred1,
            const float* __restrict__ pred2,
            float* __restrict__ out) {
    __shared__ float red[8];
    __shared__ int  isLast;
    const int tid  = threadIdx.x;
    const int lane = tid & 31;
    const int warp = tid >> 5;
    const int g    = blockIdx.x * 256 + tid;       // 128*256 = 32768 = 8192*4
    const int i    = g >> 2;                       // node id
    const int j    = g & 3;                        // sub-thread

    // node i's 32 segment partials are 96 contiguous floats; sub-thread j
    // reads floats [j*24, j*24+24) -> 6 independent float4, fully coalesced
    // across consecutive threads. 24 % 3 == 0 -> chunk starts at dim 0.
    float t0 = 0.0f, t1 = 0.0f, t2 = 0.0f;
    {
        const float4* q = reinterpret_cast<const float4*>(
            g_dotpart + (size_t)i * (NSEG * 3) + j * 24);
        float f[24];
        #pragma unroll
        for (int m = 0; m < 6; m++) {
            const float4 x = q[m];
            f[4 * m + 0] = x.x; f[4 * m + 1] = x.y;
            f[4 * m + 2] = x.z; f[4 * m + 3] = x.w;
        }
        #pragma unroll
        for (int m = 0; m < 8; m++) {
            t0 += f[3 * m + 0];
            t1 += f[3 * m + 1];
            t2 += f[3 * m + 2];
        }
    }

    // combine the 4 sub-threads (lanes 4k..4k+3 hold node k's partials)
    t0 += __shfl_xor_sync(0xFFFFFFFFu, t0, 1);
    t0 += __shfl_xor_sync(0xFFFFFFFFu, t0, 2);
    t1 += __shfl_xor_sync(0xFFFFFFFFu, t1, 1);
    t1 += __shfl_xor_sync(0xFFFFFFFFu, t1, 2);
    t2 += __shfl_xor_sync(0xFFFFFFFFu, t2, 1);
    t2 += __shfl_xor_sync(0xFFFFFFFFu, t2, 2);

    float s = 0.0f;
    if (j == 0) {
        const float deg = g_deg[i];
        g_deg[i] = 0.0f;                           // re-zero for next replay
        const float inv = 1.0f / deg;
        const float p0 = pred2[3 * i + 0] - pred1[3 * i + 0];
        const float p1 = pred2[3 * i + 1] - pred1[3 * i + 1];
        const float p2 = pred2[3 * i + 2] - pred1[3 * i + 2];
        const float e0 = p0 - t0 * inv;
        const float e1 = p1 - t1 * inv;
        const float e2 = p2 - t2 * inv;
        s = e0 * e0 + e1 * e1 + e2 * e2;
    }

    s = warp_sum(s);
    if (lane == 0) red[warp] = s;
    __syncthreads();
    if (tid == 0) {
        float v = 0.0f;
        #pragma unroll
        for (int k = 0; k < 8; k++) v += red[k];
        g_losspart[blockIdx.x] = v;
        __threadfence();
        isLast = (atomicAdd(&g_done, 1) == LBLKS - 1);
    }
    __syncthreads();

    if (isLast && warp == 0) {
        __threadfence();
        float v = __ldcg(&g_losspart[lane])
                + __ldcg(&g_losspart[lane + 32])
                + __ldcg(&g_losspart[lane + 64])
                + __ldcg(&g_losspart[lane + 96]);
        v = warp_sum(v);
        if (lane == 0) {
            out[0] = v;
            g_done = 0;                            // reset for next replay
        }
    }
}

extern "C" void kernel_launch(void* const* d_in, const int* in_sizes, int n_in,
                              void* d_out, int out_size) {
    const float* pred1 = (const float*)d_in[0];
    const float* pred2 = (const float*)d_in[1];
    const float* A     = (const float*)d_in[2];
    float* out = (float*)d_out;

    spmm_kernel<<<NCTA, THREADS>>>(pred1, pred2, A);
    loss_kernel<<<LBLKS, 256>>>(pred1, pred2, out);
}

// round 14
// speedup vs baseline: 1.0458x; 1.0458x over previous
#include <cuda_runtime.h>
#include <cstdint>

#define NN      8192
#define THREADS 640                   // 20 warps per CTA, 1 CTA/SM
#define NCTA    148
#define WPC     (THREADS / 32)        // 20
#define NWARPS  (NCTA * WPC)          // 2960
#define NSEG    32                    // column segments of 256 cols
#define SEGC    256
#define NRG     92                    // rowgroups (32*92 = 2944 working warps)
#define RU      5                     // rows per inner iteration (15 values + pad)
#define NODEMAX 56                    // max nodes per CTA in epilogue (8192/148 -> 55..56)

// scratch: __device__ globals (allocation-free rule). dotpart/degpart slots all
// have exactly one unconditional writer per launch. Counters/accumulator are
// reset by the unique last CTA each launch -> graph-replay deterministic.
__device__ float g_degpart[NWARPS * SEGC];      // 2.9 MB (only w < 2944 read)
__device__ float g_dotpart[NSEG * NN * 3];      // 3.1 MB
__device__ float g_accum;                       // loss accumulator
__device__ int   g_done;                        // phase-1 arrival counter
__device__ int   g_done2;                       // phase-2 arrival counter

__device__ __forceinline__ float warp_sum(float v) {
    v += __shfl_down_sync(0xFFFFFFFFu, v, 16);
    v += __shfl_down_sync(0xFFFFFFFFu, v, 8);
    v += __shfl_down_sync(0xFFFFFFFFu, v, 4);
    v += __shfl_down_sync(0xFFFFFFFFu, v, 2);
    v += __shfl_down_sync(0xFFFFFFFFu, v, 1);
    return v;
}

// one butterfly step: live values v[0..L-1] -> v[0..L/2-1], width W
// NOTE: all 32 lanes must be convergent.
template <int L, int W>
__device__ __forceinline__ void bstep(float* v, int lane) {
    const int hi = lane & W;
    #pragma unroll
    for (int j = 0; j < L / 2; j++) {
        const float sent = hi ? v[j] : v[j + L / 2];
        const float got  = __shfl_xor_sync(0xFFFFFFFFu, sent, W);
        v[j] = (hi ? v[j + L / 2] : v[j]) + got;
    }
}

__global__ void __launch_bounds__(THREADS, 1)
lap_kernel(const float* __restrict__ pred1,
           const float* __restrict__ pred2,
           const float* __restrict__ A,
           float* __restrict__ out) {
    __shared__ float sdeg[NODEMAX];
    __shared__ float sdot[NODEMAX * 3];
    __shared__ float sloss[NODEMAX];

    const int tid  = threadIdx.x;
    const int lane = tid & 31;
    const int warp = tid >> 5;

    // ================= phase 1: streaming pass over A (exact R9) =============
    const int w    = blockIdx.x * WPC + warp;
    const int seg  = w & (NSEG - 1);
    const int rg   = w >> 5;
    const int col0 = seg * SEGC + lane * 8;        // this lane's 8 columns
    const bool active = (rg < NRG);
    const int r0   = active ? (rg * NN) / NRG : 0;
    const int r1   = active ? ((rg + 1) * NN) / NRG : 0;

    // hoist p = pred2 - pred1 for this lane's 8 columns: p[jc][d], 24 regs
    float p[8][3];
    {
        const float4* q1 = reinterpret_cast<const float4*>(pred1 + (size_t)col0 * 3);
        const float4* q2 = reinterpret_cast<const float4*>(pred2 + (size_t)col0 * 3);
        float tmp[24];
        #pragma unroll
        for (int k = 0; k < 6; k++) {
            const float4 a = q2[k];
            const float4 b = q1[k];
            tmp[4 * k + 0] = a.x - b.x;
            tmp[4 * k + 1] = a.y - b.y;
            tmp[4 * k + 2] = a.z - b.z;
            tmp[4 * k + 3] = a.w - b.w;
        }
        #pragma unroll
        for (int j = 0; j < 24; j++) p[j / 3][j % 3] = tmp[j];
    }

    float dg[8];
    #pragma unroll
    for (int j = 0; j < 8; j++) dg[j] = 0.0f;

    const float4* __restrict__ Abase =
        reinterpret_cast<const float4*>(A + (size_t)r0 * NN + col0);
    const int stride4 = NN / 4;
    const int rows = r1 - r0;

    int r = 0;
    for (; r + RU <= rows; r += RU) {
        // front-batch 2*RU = 10 independent loads
        float4 av[RU][2];
        #pragma unroll
        for (int k = 0; k < RU; k++) {
            const float4* rp = Abase + (size_t)(r + k) * stride4;
            av[k][0] = __ldcs(rp);
            av[k][1] = __ldcs(rp + 1);
        }

        float v[16];
        #pragma unroll
        for (int k = 0; k < RU; k++) {
            const float4 a0 = av[k][0], a1 = av[k][1];
            #pragma unroll
            for (int d = 0; d < 3; d++) {
                v[k * 3 + d] =
                    a0.x * p[0][d] + a0.y * p[1][d] + a0.z * p[2][d] + a0.w * p[3][d] +
                    a1.x * p[4][d] + a1.y * p[5][d] + a1.z * p[6][d] + a1.w * p[7][d];
            }
            dg[0] += a0.x; dg[1] += a0.y; dg[2] += a0.z; dg[3] += a0.w;
            dg[4] += a1.x; dg[5] += a1.y; dg[6] += a1.z; dg[7] += a1.w;
        }
        v[15] = 0.0f;                              // pad to 16

        bstep<16, 16>(v, lane);
        bstep<8, 8>(v, lane);
        bstep<4, 4>(v, lane);
        bstep<2, 2>(v, lane);
        v[0] += __shfl_xor_sync(0xFFFFFFFFu, v[0], 1);

        const int k = lane >> 1;                   // value index 0..15
        if ((lane & 1) == 0 && k < 15)             // contiguous 60B store
            g_dotpart[((size_t)seg * NN + (r0 + r)) * 3 + k] = v[0];
    }

    // tail rows (<= RU-1): plain warp reductions, fully convergent
    for (; r < rows; r++) {
        const float4* rp = Abase + (size_t)r * stride4;
        const float4 a0 = __ldcs(rp);
        const float4 a1 = __ldcs(rp + 1);
        float t0 = warp_sum(
            a0.x * p[0][0] + a0.y * p[1][0] + a0.z * p[2][0] + a0.w * p[3][0] +
            a1.x * p[4][0] + a1.y * p[5][0] + a1.z * p[6][0] + a1.w * p[7][0]);
        float t1 = warp_sum(
            a0.x * p[0][1] + a0.y * p[1][1] + a0.z * p[2][1] + a0.w * p[3][1] +
            a1.x * p[4][1] + a1.y * p[5][1] + a1.z * p[6][1] + a1.w * p[7][1]);
        float t2 = warp_sum(
            a0.x * p[0][2] + a0.y * p[1][2] + a0.z * p[2][2] + a0.w * p[3][2] +
            a1.x * p[4][2] + a1.y * p[5][2] + a1.z * p[6][2] + a1.w * p[7][2]);
        dg[0] += a0.x; dg[1] += a0.y; dg[2] += a0.z; dg[3] += a0.w;
        dg[4] += a1.x; dg[5] += a1.y; dg[6] += a1.z; dg[7] += a1.w;
        if (lane == 0) {
            float* dst = g_dotpart + ((size_t)seg * NN + (r0 + r)) * 3;
            dst[0] = t0; dst[1] = t1; dst[2] = t2;
        }
    }

    // flush deg partials (coalesced; inactive warps write zeros to unread slot)
    {
        float* dst = g_degpart + (size_t)w * SEGC + lane * 8;
        float4 d0; d0.x = dg[0]; d0.y = dg[1]; d0.z = dg[2]; d0.w = dg[3];
        float4 d1; d1.x = dg[4]; d1.y = dg[5]; d1.z = dg[6]; d1.w = dg[7];
        *reinterpret_cast<float4*>(dst)     = d0;
        *reinterpret_cast<float4*>(dst + 4) = d1;
    }

    // ============ grid-wide join: safe because grid==148, 1 CTA/SM ===========
    __syncthreads();
    if (tid == 0) {
        __threadfence();
        atomicAdd(&g_done, 1);
        volatile int* dp = &g_done;
        while (*dp < NCTA) { __nanosleep(64); }
    }
    __syncthreads();
    __threadfence();                               // acquire all CTAs' stores

    // ================= phase 2: epilogue across all 148 CTAs =================
    const int n0 = (blockIdx.x * NN) / NCTA;
    const int n1 = ((blockIdx.x + 1) * NN) / NCTA;
    const int nn = n1 - n0;                        // 55 or 56

    for (int j = tid; j < NODEMAX; j += THREADS) { // zero smem accumulators
        sdeg[j] = 0.0f;
        sdot[3 * j + 0] = 0.0f; sdot[3 * j + 1] = 0.0f; sdot[3 * j + 2] = 0.0f;
    }
    __syncthreads();

    // deg: sum 92 rowgroup partials per node (coalesced: consecutive idx -> consecutive c)
    for (int idx = tid; idx < NRG * NODEMAX; idx += THREADS) {
        const int nrel = idx % NODEMAX;
        const int rgi  = idx / NODEMAX;
        if (nrel < nn) {
            const int i = n0 + nrel;
            const int sg = i >> 8;
            const int c  = i & (SEGC - 1);
            atomicAdd(&sdeg[nrel], g_degpart[((size_t)rgi * NSEG + sg) * SEGC + c]);
        }
    }
    // dot: sum 32 segment partials per node (coalesced: d fastest, node next)
    for (int idx = tid; idx < NSEG * NODEMAX * 3; idx += THREADS) {
        const int d    = idx % 3;
        const int nrel = (idx / 3) % NODEMAX;
        const int sg   = idx / (3 * NODEMAX);
        if (nrel < nn) {
            const int i = n0 + nrel;
            atomicAdd(&sdot[nrel * 3 + d], g_dotpart[((size_t)sg * NN + i) * 3 + d]);
        }
    }
    __syncthreads();

    if (tid < nn) {
        const int i = n0 + tid;
        const float inv = 1.0f / sdeg[tid];
        const float p0 = pred2[3 * i + 0] - pred1[3 * i + 0];
        const float p1 = pred2[3 * i + 1] - pred1[3 * i + 1];
        const float p2 = pred2[3 * i + 2] - pred1[3 * i + 2];
        const float e0 = p0 - sdot[3 * tid + 0] * inv;
        const float e1 = p1 - sdot[3 * tid + 1] * inv;
        const float e2 = p2 - sdot[3 * tid + 2] * inv;
        sloss[tid] = e0 * e0 + e1 * e1 + e2 * e2;
    }
    __syncthreads();

    if (tid == 0) {
        float v = 0.0f;
        for (int k = 0; k < nn; k++) v += sloss[k];
        atomicAdd(&g_accum, v);
        __threadfence();
        const int d2 = atomicAdd(&g_done2, 1);
        if (d2 == NCTA - 1) {                      // unique last CTA finalizes
            __threadfence();
            out[0] = *((volatile float*)&g_accum);
            g_accum = 0.0f;                        // reset for next replay
            g_done2 = 0;
            g_done  = 0;
        }
    }
}

extern "C" void kernel_launch(void* const* d_in, const int* in_sizes, int n_in,
                              void* d_out, int out_size) {
    const float* pred1 = (const float*)d_in[0];
    const float* pred2 = (const float*)d_in[1];
    const float* A     = (const float*)d_in[2];
    float* out = (float*)d_out;

    lap_kernel<<<NCTA, THREADS>>>(pred1, pred2, A, out);
}

// round 15
// speedup vs baseline: 1.1415x; 1.0914x over previous
#include <cuda_runtime.h>
#include <cstdint>

#define NN      8192
#define THREADS 640                   // 20 warps per CTA
#define NCTA    148
#define WPC     (THREADS / 32)        // 20
#define NWARPS  (NCTA * WPC)          // 2960
#define NSEG    32                    // column segments of 256 cols
#define SEGC    256
#define NRG     92                    // rowgroups (32*92 = 2944 working warps)
#define RU      5                     // rows per inner iteration (15 values + pad)
#define RBLKS   64                    // reduce grid: CTA = 128 nodes (half segment)

// scratch: __device__ globals (allocation-free rule). Every read slot has
// exactly one unconditional writer per launch; g_done reset by the unique
// last reduce block -> graph-replay deterministic.
__device__ float g_degpart[NWARPS * SEGC];      // 2.9 MB (only w < 2944 read)
__device__ float g_dotpart[NSEG * NN * 3];      // 3.1 MB
__device__ float g_losspart[RBLKS];
__device__ int   g_done;

__device__ __forceinline__ float warp_sum(float v) {
    v += __shfl_down_sync(0xFFFFFFFFu, v, 16);
    v += __shfl_down_sync(0xFFFFFFFFu, v, 8);
    v += __shfl_down_sync(0xFFFFFFFFu, v, 4);
    v += __shfl_down_sync(0xFFFFFFFFu, v, 2);
    v += __shfl_down_sync(0xFFFFFFFFu, v, 1);
    return v;
}

// one butterfly step: live values v[0..L-1] -> v[0..L/2-1], width W
// NOTE: all 32 lanes must be convergent.
template <int L, int W>
__device__ __forceinline__ void bstep(float* v, int lane) {
    const int hi = lane & W;
    #pragma unroll
    for (int j = 0; j < L / 2; j++) {
        const float sent = hi ? v[j] : v[j + L / 2];
        const float got  = __shfl_xor_sync(0xFFFFFFFFu, sent, W);
        v[j] = (hi ? v[j + L / 2] : v[j]) + got;
    }
}

// ---------- kernel A: one streaming pass over A (exact R9 config) ----------
__global__ void __launch_bounds__(THREADS, 1)
spmm_kernel(const float* __restrict__ pred1,
            const float* __restrict__ pred2,
            const float* __restrict__ A) {
    const int tid  = threadIdx.x;
    const int lane = tid & 31;
    const int warp = tid >> 5;

    const int w    = blockIdx.x * WPC + warp;
    const int seg  = w & (NSEG - 1);
    const int rg   = w >> 5;
    const int col0 = seg * SEGC + lane * 8;        // this lane's 8 columns
    const bool active = (rg < NRG);
    const int r0   = active ? (rg * NN) / NRG : 0;
    const int r1   = active ? ((rg + 1) * NN) / NRG : 0;

    // hoist p = pred2 - pred1 for this lane's 8 columns: p[jc][d], 24 regs
    float p[8][3];
    {
        const float4* q1 = reinterpret_cast<const float4*>(pred1 + (size_t)col0 * 3);
        const float4* q2 = reinterpret_cast<const float4*>(pred2 + (size_t)col0 * 3);
        float tmp[24];
        #pragma unroll
        for (int k = 0; k < 6; k++) {
            const float4 a = q2[k];
            const float4 b = q1[k];
            tmp[4 * k + 0] = a.x - b.x;
            tmp[4 * k + 1] = a.y - b.y;
            tmp[4 * k + 2] = a.z - b.z;
            tmp[4 * k + 3] = a.w - b.w;
        }
        #pragma unroll
        for (int j = 0; j < 24; j++) p[j / 3][j % 3] = tmp[j];
    }

    float dg[8];
    #pragma unroll
    for (int j = 0; j < 8; j++) dg[j] = 0.0f;

    const float4* __restrict__ Abase =
        reinterpret_cast<const float4*>(A + (size_t)r0 * NN + col0);
    const int stride4 = NN / 4;
    const int rows = r1 - r0;

    int r = 0;
    for (; r + RU <= rows; r += RU) {
        // front-batch 2*RU = 10 independent loads
        float4 av[RU][2];
        #pragma unroll
        for (int k = 0; k < RU; k++) {
            const float4* rp = Abase + (size_t)(r + k) * stride4;
            av[k][0] = __ldcs(rp);
            av[k][1] = __ldcs(rp + 1);
        }

        float v[16];
        #pragma unroll
        for (int k = 0; k < RU; k++) {
            const float4 a0 = av[k][0], a1 = av[k][1];
            #pragma unroll
            for (int d = 0; d < 3; d++) {
                v[k * 3 + d] =
                    a0.x * p[0][d] + a0.y * p[1][d] + a0.z * p[2][d] + a0.w * p[3][d] +
                    a1.x * p[4][d] + a1.y * p[5][d] + a1.z * p[6][d] + a1.w * p[7][d];
            }
            dg[0] += a0.x; dg[1] += a0.y; dg[2] += a0.z; dg[3] += a0.w;
            dg[4] += a1.x; dg[5] += a1.y; dg[6] += a1.z; dg[7] += a1.w;
        }
        v[15] = 0.0f;                              // pad to 16

        // multi-value butterfly: after 5 steps, lane pair floor(l/2)
        // holds the full 32-lane sum of value floor(l/2)
        bstep<16, 16>(v, lane);
        bstep<8, 8>(v, lane);
        bstep<4, 4>(v, lane);
        bstep<2, 2>(v, lane);
        v[0] += __shfl_xor_sync(0xFFFFFFFFu, v[0], 1);

        const int k = lane >> 1;                   // value index 0..15
        if ((lane & 1) == 0 && k < 15)             // contiguous 60B store
            g_dotpart[((size_t)seg * NN + (r0 + r)) * 3 + k] = v[0];
    }

    // tail rows (<= RU-1): plain warp reductions, fully convergent
    for (; r < rows; r++) {
        const float4* rp = Abase + (size_t)r * stride4;
        const float4 a0 = __ldcs(rp);
        const float4 a1 = __ldcs(rp + 1);
        float t0 = warp_sum(
            a0.x * p[0][0] + a0.y * p[1][0] + a0.z * p[2][0] + a0.w * p[3][0] +
            a1.x * p[4][0] + a1.y * p[5][0] + a1.z * p[6][0] + a1.w * p[7][0]);
        float t1 = warp_sum(
            a0.x * p[0][1] + a0.y * p[1][1] + a0.z * p[2][1] + a0.w * p[3][1] +
            a1.x * p[4][1] + a1.y * p[5][1] + a1.z * p[6][1] + a1.w * p[7][1]);
        float t2 = warp_sum(
            a0.x * p[0][2] + a0.y * p[1][2] + a0.z * p[2][2] + a0.w * p[3][2] +
            a1.x * p[4][2] + a1.y * p[5][2] + a1.z * p[6][2] + a1.w * p[7][2]);
        dg[0] += a0.x; dg[1] += a0.y; dg[2] += a0.z; dg[3] += a0.w;
        dg[4] += a1.x; dg[5] += a1.y; dg[6] += a1.z; dg[7] += a1.w;
        if (lane == 0) {
            float* dst = g_dotpart + ((size_t)seg * NN + (r0 + r)) * 3;
            dst[0] = t0; dst[1] = t1; dst[2] = t2;
        }
    }

    // flush deg partials (coalesced; inactive warps write zeros to unread slot)
    {
        float* dst = g_degpart + (size_t)w * SEGC + lane * 8;
        float4 d0; d0.x = dg[0]; d0.y = dg[1]; d0.z = dg[2]; d0.w = dg[3];
        float4 d1; d1.x = dg[4]; d1.y = dg[5]; d1.z = dg[6]; d1.w = dg[7];
        *reinterpret_cast<float4*>(dst)     = d0;
        *reinterpret_cast<float4*>(dst + 4) = d1;
    }
}

// ---------- kernel B: segment-aligned coalesced reduce + fused final ----------
// CTA b owns 128 nodes = half of segment (b>>1). All partial reads coalesced.
__global__ void __launch_bounds__(256)
reduce_kernel(const float* __restrict__ pred1,
              const float* __restrict__ pred2,
              float* __restrict__ out) {
    __shared__ float sdeg2[256];
    __shared__ float sdeg[128];
    __shared__ float sdot[384];
    __shared__ float red[8];
    __shared__ int  isLast;

    const int tid  = threadIdx.x;
    const int lane = tid & 31;
    const int warp = tid >> 5;
    const int b    = blockIdx.x;
    const int s    = b >> 1;                       // segment
    const int cb   = (b & 1) * 128;                // column base within segment
    const int nbase = b * 128;                     // first node of this CTA

    // ---- deg: column c summed over 92 rowgroups, split 46/46 across halves ----
    {
        const int cc   = tid & 127;
        const int half = tid >> 7;
        const float* base = g_degpart + (size_t)s * SEGC + cb + cc;
        float acc = 0.0f;
        const int rg0 = half * 46;
        #pragma unroll 23
        for (int rg = rg0; rg < rg0 + 46; rg++)
            acc += base[(size_t)rg * (NSEG * SEGC)];
        sdeg2[tid] = acc;
    }

    // ---- dot: 384 contiguous floats per segment-block, summed over 32 segs ----
    {
        const float* base = g_dotpart + (size_t)nbase * 3;   // + sg*NN*3
        float acc0 = 0.0f, acc1 = 0.0f;
        #pragma unroll 8
        for (int sg = 0; sg < NSEG; sg++) {
            const float* q = base + (size_t)sg * (NN * 3);
            acc0 += q[tid];
            if (tid < 128) acc1 += q[256 + tid];
        }
        sdot[tid] = acc0;
        if (tid < 128) sdot[256 + tid] = acc1;
    }
    __syncthreads();
    if (tid < 128) sdeg[tid] = sdeg2[tid] + sdeg2[tid + 128];
    __syncthreads();

    // ---- per-node loss (nodes nbase..nbase+127), block reduce ----
    float sl = 0.0f;
    if (tid < 128) {
        const int i = nbase + tid;
        const float inv = 1.0f / sdeg[tid];
        const float p0 = pred2[3 * i + 0] - pred1[3 * i + 0];
        const float p1 = pred2[3 * i + 1] - pred1[3 * i + 1];
        const float p2 = pred2[3 * i + 2] - pred1[3 * i + 2];
        const float e0 = p0 - sdot[3 * tid + 0] * inv;
        const float e1 = p1 - sdot[3 * tid + 1] * inv;
        const float e2 = p2 - sdot[3 * tid + 2] * inv;
        sl = e0 * e0 + e1 * e1 + e2 * e2;
    }
    sl = warp_sum(sl);
    if (lane == 0) red[warp] = sl;
    __syncthreads();
    if (tid == 0) {
        float v = 0.0f;
        #pragma unroll
        for (int k = 0; k < 8; k++) v += red[k];
        g_losspart[b] = v;
        __threadfence();
        isLast = (atomicAdd(&g_done, 1) == RBLKS - 1);
    }
    __syncthreads();

    if (isLast && warp == 0) {
        __threadfence();
        float v = __ldcg(&g_losspart[lane]) + __ldcg(&g_losspart[lane + 32]);
        v = warp_sum(v);
        if (lane == 0) {
            out[0] = v;
            g_done = 0;                            // reset for next replay
        }
    }
}

extern "C" void kernel_launch(void* const* d_in, const int* in_sizes, int n_in,
                              void* d_out, int out_size) {
    const float* pred1 = (const float*)d_in[0];
    const float* pred2 = (const float*)d_in[1];
    const float* A     = (const float*)d_in[2];
    float* out = (float*)d_out;

    spmm_kernel<<<NCTA, THREADS>>>(pred1, pred2, A);
    reduce_kernel<<<RBLKS, 256>>>(pred1, pred2, out);
}